// round 15
// baseline (speedup 1.0000x reference)
#include <cuda_runtime.h>
#include <cuda_fp16.h>
#include <cstdint>

// ---------------------------------------------------------------------------
// Problem constants
// ---------------------------------------------------------------------------
#define B_   8
#define N_   1024
#define D_   512
#define C_   1024
#define Q_   8
#define M_   (B_ * N_)      // 8192 rows
#define D4_  (D_ / 4)

// Output layout (all float32): [quantized_out M*D][indices M*Q][losses Q]
#define OUT_IDX_OFF  ((size_t)M_ * D_)
#define OUT_LOSS_OFF ((size_t)M_ * D_ + (size_t)M_ * Q_)

// ---------------------------------------------------------------------------
// Scratch (__device__ globals — allocation-free)
// ---------------------------------------------------------------------------
__device__ float g_residual[M_ * D_];
__device__ char  g_resq[M_ * D_];          // int8(residual)
__device__ float g_rs[M_];                 // per-row residual scale
__device__ char  g_cbq[Q_ * C_ * D_];      // int8(codebooks)
__device__ float g_cs[Q_ * C_];            // per-codeword scale
__device__ float g_csmax[Q_];              // max codeword scale per layer
__device__ float g_e2[Q_ * C_];
__device__ float g_loss[Q_];
__device__ __half g_dots[M_ * C_];         // fp16(-2*dot) matrix (16.7 MB)

// ---------------------------------------------------------------------------
// PTX helpers (sm_80-level: cp.async / ldmatrix / mma.sync s8)
// ---------------------------------------------------------------------------
__device__ __forceinline__ uint32_t smem_to_u32(const void* p) {
    uint32_t a;
    asm("{ .reg .u64 t; cvta.to.shared.u64 t, %1; cvt.u32.u64 %0, t; }"
        : "=r"(a) : "l"(p));
    return a;
}
__device__ __forceinline__ void cp16(uint32_t dst, const void* src) {
    asm volatile("cp.async.cg.shared.global [%0], [%1], 16;"
                 :: "r"(dst), "l"(src));
}
#define CP_COMMIT() asm volatile("cp.async.commit_group;" ::: "memory")
#define CP_WAIT(n)  asm volatile("cp.async.wait_group %0;" :: "n"(n) : "memory")

__device__ __forceinline__ void ldm_x4(uint32_t* r, uint32_t addr) {
    asm volatile("ldmatrix.sync.aligned.m8n8.x4.shared.b16 {%0,%1,%2,%3}, [%4];"
                 : "=r"(r[0]), "=r"(r[1]), "=r"(r[2]), "=r"(r[3]) : "r"(addr));
}
__device__ __forceinline__ void mma16832_s8(int* d, const uint32_t* a,
                                            uint32_t b0, uint32_t b1) {
    asm volatile(
        "mma.sync.aligned.m16n8k32.row.col.s32.s8.s8.s32 "
        "{%0,%1,%2,%3}, {%4,%5,%6,%7}, {%8,%9}, {%0,%1,%2,%3};"
        : "+r"(d[0]), "+r"(d[1]), "+r"(d[2]), "+r"(d[3])
        : "r"(a[0]), "r"(a[1]), "r"(a[2]), "r"(a[3]), "r"(b0), "r"(b1));
}

// monotone float -> uint transform (order-preserving, for exact-rerank min)
__device__ __forceinline__ uint32_t ford(float f) {
    uint32_t u = __float_as_uint(f);
    return (u & 0x80000000u) ? ~u : (u | 0x80000000u);
}

__device__ __forceinline__ char4 quant4(float4 v, float inv) {
    char4 c;
    c.x = (char)__float2int_rn(v.x * inv);
    c.y = (char)__float2int_rn(v.y * inv);
    c.z = (char)__float2int_rn(v.z * inv);
    c.w = (char)__float2int_rn(v.w * inv);
    return c;
}
__device__ __forceinline__ float max4(float4 v) {
    return fmaxf(fmaxf(fabsf(v.x), fabsf(v.y)), fmaxf(fabsf(v.z), fabsf(v.w)));
}

// ---------------------------------------------------------------------------
// init: residual = x, int8 quantize (warp per row), zero loss
// ---------------------------------------------------------------------------
__global__ void init_kernel(const float* __restrict__ x) {
    const int lane = threadIdx.x & 31, wid = threadIdx.x >> 5;
    const int row = blockIdx.x * 8 + wid;
    const float4* xr = (const float4*)(x + (size_t)row * D_);
    float4* rr = (float4*)(g_residual + (size_t)row * D_);
    float4 v[4];
    float mx = 0.f;
#pragma unroll
    for (int k = 0; k < 4; k++) {
        v[k] = xr[lane + 32 * k];
        rr[lane + 32 * k] = v[k];
        mx = fmaxf(mx, max4(v[k]));
    }
#pragma unroll
    for (int o = 16; o > 0; o >>= 1)
        mx = fmaxf(mx, __shfl_xor_sync(0xffffffffu, mx, o));
    mx = fmaxf(mx, 1e-12f);
    const float inv = 127.f / mx;
    char4* qr = (char4*)(g_resq + (size_t)row * D_);
#pragma unroll
    for (int k = 0; k < 4; k++) qr[lane + 32 * k] = quant4(v[k], inv);
    if (lane == 0) g_rs[row] = mx * (1.f / 127.f);
    if (blockIdx.x == 0 && threadIdx.x < Q_) g_loss[threadIdx.x] = 0.f;
}

// ---------------------------------------------------------------------------
// prep: e2 + int8 quantize for all codebook rows (warp per row)
// ---------------------------------------------------------------------------
__global__ void prep_kernel(const float* __restrict__ cbs) {
    const int w = (blockIdx.x * blockDim.x + threadIdx.x) >> 5;
    const int lane = threadIdx.x & 31;
    if (w >= Q_ * C_) return;
    const float4* row = (const float4*)(cbs + (size_t)w * D_);
    float4 v[4];
    float s2 = 0.f, mx = 0.f;
#pragma unroll
    for (int k = 0; k < 4; k++) {
        v[k] = row[lane + 32 * k];
        s2 = fmaf(v[k].x, v[k].x, s2); s2 = fmaf(v[k].y, v[k].y, s2);
        s2 = fmaf(v[k].z, v[k].z, s2); s2 = fmaf(v[k].w, v[k].w, s2);
        mx = fmaxf(mx, max4(v[k]));
    }
#pragma unroll
    for (int o = 16; o > 0; o >>= 1) {
        s2 += __shfl_xor_sync(0xffffffffu, s2, o);
        mx = fmaxf(mx, __shfl_xor_sync(0xffffffffu, mx, o));
    }
    mx = fmaxf(mx, 1e-12f);
    const float inv = 127.f / mx;
    char4* qr = (char4*)(g_cbq + (size_t)w * D_);
#pragma unroll
    for (int k = 0; k < 4; k++) qr[lane + 32 * k] = quant4(v[k], inv);
    if (lane == 0) {
        g_e2[w] = s2;
        const float s = mx * (1.f / 127.f);
        g_cs[w] = s;
        atomicMax((unsigned*)&g_csmax[w / C_], __float_as_uint(s));
    }
}

// ---------------------------------------------------------------------------
// Screen GEMM: int8 x int8 -> s32, CTA 128x128, K=512, k-chunk 64 int8
// (64 B rows — byte-identical smem geometry to the proven fp16 pipeline).
// 8 warps @ 64x32, 4-stage cp.async pipeline, 8 chunks.
// Epilogue writes fp16(-2 * acc * s_r * s_c) to g_dots.
// ---------------------------------------------------------------------------
#define KCHB   64              // 64 int8 per chunk row (64 bytes)
#define NCH    8               // 512 / 64
#define ROWB   80u             // 64 B payload + 16 B pad
#define TILEB  10240u          // 128 * 80
#define STAGEB 20480u          // A + B tiles
#define OFF_SC 81920u          // 128 codeword scales
#define SMEM_BYTES 82432u

__global__ void __launch_bounds__(256, 2) screen_kernel(int q) {
    extern __shared__ __align__(128) char smem[];
    const uint32_t sm = smem_to_u32(smem);

    const int t = threadIdx.x;
    const int lane = t & 31, wid = t >> 5;
    const int warp_m = (wid >> 2) * 64;     // 0 or 64
    const int warp_n = (wid & 3) * 32;      // 0..96
    const int bm0 = blockIdx.x * 128;
    const int c0  = blockIdx.y * 128;

    const char* Bq = g_cbq + (size_t)q * C_ * D_;
    float* scs = (float*)(smem + OFF_SC);
    if (t < 128) scs[t] = g_cs[q * C_ + c0 + t];

    // loader: row = t>>1 (128 rows), granule pair lg = t&1 (32 B each)
    const int lrow = t >> 1;
    const int lg   = t & 1;
    const char* pa = g_resq + (size_t)(bm0 + lrow) * D_ + lg * 32;
    const char* pb = Bq + (size_t)(c0 + lrow) * D_ + lg * 32;
    const uint32_t sdst = sm + lrow * ROWB + lg * 32;

    uint32_t a_off[4];
#pragma unroll
    for (int ma = 0; ma < 4; ma++)
        a_off[ma] = (uint32_t)((warp_m + ma * 16 + (lane & 15)) * ROWB +
                               (lane >> 4) * 16);
    uint32_t b_off[2];
#pragma unroll
    for (int p = 0; p < 2; p++)
        b_off[p] = (uint32_t)((warp_n + p * 16 + ((lane >> 4) << 3) + (lane & 7)) * ROWB +
                              ((lane >> 3) & 1) * 16);

    int acc[4][4][4];
#pragma unroll
    for (int i = 0; i < 4; i++)
#pragma unroll
        for (int j = 0; j < 4; j++)
#pragma unroll
            for (int e = 0; e < 4; e++) acc[i][j][e] = 0;

    auto issue_loads = [&](int kk) {
        const uint32_t buf = (uint32_t)(kk & 3) * STAGEB + sdst;
        const int col = kk * KCHB;
        cp16(buf,              pa + col);
        cp16(buf + 16,         pa + col + 16);
        cp16(buf + TILEB,      pb + col);
        cp16(buf + TILEB + 16, pb + col + 16);
        CP_COMMIT();
    };

    issue_loads(0); issue_loads(1); issue_loads(2);

    for (int cc = 0; cc < NCH; cc++) {
        if (cc < NCH - 2)       CP_WAIT(2);
        else if (cc == NCH - 2) CP_WAIT(1);
        else                    CP_WAIT(0);
        __syncthreads();

        const uint32_t buf = sm + (uint32_t)(cc & 3) * STAGEB;
#pragma unroll
        for (int k = 0; k < 2; k++) {           // two k=32 steps (bytes +0/+32)
            uint32_t a[4][4], bb[2][4];
#pragma unroll
            for (int ma = 0; ma < 4; ma++)
                ldm_x4(a[ma], buf + a_off[ma] + k * 32);
#pragma unroll
            for (int p = 0; p < 2; p++)
                ldm_x4(bb[p], buf + TILEB + b_off[p] + k * 32);
#pragma unroll
            for (int ma = 0; ma < 4; ma++)
#pragma unroll
                for (int nb = 0; nb < 4; nb++) {
                    const uint32_t* bp = bb[nb >> 1];
                    mma16832_s8(acc[ma][nb], a[ma],
                                bp[(nb & 1) * 2], bp[(nb & 1) * 2 + 1]);
                }
        }
        if (cc + 3 < NCH) issue_loads(cc + 3);
        __syncthreads();
    }

    // epilogue: dot = acc * s_r * s_c; write fp16(-2*dot) pairs
    const int g = lane >> 2, tg = lane & 3;
#pragma unroll
    for (int ma = 0; ma < 4; ma++) {
#pragma unroll
        for (int half = 0; half < 2; half++) {
            const int row = bm0 + warp_m + ma * 16 + half * 8 + g;
            const float sr = g_rs[row];
            __half* krow = g_dots + (size_t)row * C_ + c0 + warp_n;
#pragma unroll
            for (int nb = 0; nb < 4; nb++) {
                const int cl = warp_n + nb * 8 + tg * 2;
                const float d0 = (float)acc[ma][nb][half * 2 + 0] * sr * scs[cl];
                const float d1 = (float)acc[ma][nb][half * 2 + 1] * sr * scs[cl + 1];
                __half2 hv = __floats2half2_rn(-2.f * d0, -2.f * d1);
                *(__half2*)(krow + nb * 8 + tg * 2) = hv;
            }
        }
    }
}

// ---------------------------------------------------------------------------
// rerank + update: one warp per row. Approx keys e2 + fp16 dots; per-row
// adaptive margin (6-sigma int8-error model); exact fp32 re-rank; residual
// update / loss / int8 re-quantize / index write.
// ---------------------------------------------------------------------------
__global__ void __launch_bounds__(256) rerank_kernel(
    const float* __restrict__ cbs, float* __restrict__ idx_out, int q, int last) {
    const int lane = threadIdx.x & 31, wid = threadIdx.x >> 5;
    const int row = blockIdx.x * 8 + wid;
    const float* cb = cbs + (size_t)q * C_ * D_;
    __shared__ float wsum[8];
    __shared__ float e2s[C_];

    {
        const float* e2q = g_e2 + q * C_;
#pragma unroll
        for (int i = 0; i < C_ / 256; i++)
            e2s[threadIdx.x + 256 * i] = e2q[threadIdx.x + 256 * i];
    }
    __syncthreads();

    // residual row (float4, lane-strided) + ||r||^2
    const float4* rres = (const float4*)(g_residual + (size_t)row * D_);
    float4 res4[4];
    float r2 = 0.f;
#pragma unroll
    for (int k = 0; k < 4; k++) {
        res4[k] = rres[lane + 32 * k];
        r2 = fmaf(res4[k].x, res4[k].x, r2); r2 = fmaf(res4[k].y, res4[k].y, r2);
        r2 = fmaf(res4[k].z, res4[k].z, r2); r2 = fmaf(res4[k].w, res4[k].w, r2);
    }
#pragma unroll
    for (int o = 16; o > 0; o >>= 1) r2 += __shfl_xor_sync(0xffffffffu, r2, o);

    // adaptive rescue margin (6-sigma int8 dot error + fp16 storage)
    const float sr = g_rs[row];
    const float scm = g_csmax[q];
    const float err6 = 39.2f * sqrtf(sr * sr * 1.1f + (r2 * (1.f / 512.f)) * scm * scm);
    const float delta = 4.f * err6 + 0.01f * sqrtf(r2) + 0.3f;

    // approx keys + row min (value only)
    const __half* drow = g_dots + (size_t)row * C_;
    float keys[32];
    float mn = 3.4e38f;
#pragma unroll
    for (int kp = 0; kp < 32; kp++) {
        keys[kp] = e2s[kp * 32 + lane] + __half2float(drow[kp * 32 + lane]);
        mn = fminf(mn, keys[kp]);
    }
#pragma unroll
    for (int o = 16; o > 0; o >>= 1)
        mn = fminf(mn, __shfl_xor_sync(0xffffffffu, mn, o));
    const float thresh = mn + delta;

    // exact fp32 re-rank of margin candidates
    unsigned long long bestx = ~0ull;
#pragma unroll
    for (int kp = 0; kp < 32; kp++) {
        unsigned mask = __ballot_sync(0xffffffffu, keys[kp] <= thresh);
        while (mask) {
            const int b = __ffs(mask) - 1;
            mask &= mask - 1;
            const int cand = kp * 32 + b;
            const float4* cr4 = (const float4*)(cb + (size_t)cand * D_);
            float dot = 0.f;
#pragma unroll
            for (int k = 0; k < 4; k++) {
                const float4 c4 = cr4[lane + 32 * k];
                dot = fmaf(res4[k].x, c4.x, dot); dot = fmaf(res4[k].y, c4.y, dot);
                dot = fmaf(res4[k].z, c4.z, dot); dot = fmaf(res4[k].w, c4.w, dot);
            }
#pragma unroll
            for (int o = 16; o > 0; o >>= 1)
                dot += __shfl_xor_sync(0xffffffffu, dot, o);
            const float ek = e2s[cand] - 2.f * dot;
            unsigned long long p =
                ((unsigned long long)ford(ek) << 32) | (unsigned)cand;
            if (p < bestx) bestx = p;
        }
    }
    const int bidx = (int)(bestx & 0xFFFFFFFFull);
    if (lane == 0 && idx_out)
        idx_out[(size_t)row * Q_ + q] = (float)bidx;

    // update residual, loss, int8 re-quantize
    const float4* cw4 = (const float4*)(cb + (size_t)bidx * D_);
    float4* wres = (float4*)(g_residual + (size_t)row * D_);
    float4 rn4[4];
    float sq = 0.f, mx = 0.f;
#pragma unroll
    for (int k = 0; k < 4; k++) {
        const float4 c4 = cw4[lane + 32 * k];
        rn4[k].x = res4[k].x - c4.x; rn4[k].y = res4[k].y - c4.y;
        rn4[k].z = res4[k].z - c4.z; rn4[k].w = res4[k].w - c4.w;
        wres[lane + 32 * k] = rn4[k];
        sq = fmaf(rn4[k].x, rn4[k].x, sq); sq = fmaf(rn4[k].y, rn4[k].y, sq);
        sq = fmaf(rn4[k].z, rn4[k].z, sq); sq = fmaf(rn4[k].w, rn4[k].w, sq);
        mx = fmaxf(mx, max4(rn4[k]));
    }
    if (!last) {
#pragma unroll
        for (int o = 16; o > 0; o >>= 1)
            mx = fmaxf(mx, __shfl_xor_sync(0xffffffffu, mx, o));
        mx = fmaxf(mx, 1e-12f);
        const float inv = 127.f / mx;
        char4* qr = (char4*)(g_resq + (size_t)row * D_);
#pragma unroll
        for (int k = 0; k < 4; k++) qr[lane + 32 * k] = quant4(rn4[k], inv);
        if (lane == 0) g_rs[row] = mx * (1.f / 127.f);
    }
#pragma unroll
    for (int o = 16; o > 0; o >>= 1) sq += __shfl_xor_sync(0xffffffffu, sq, o);
    if (lane == 0) wsum[wid] = sq;
    __syncthreads();
    if (threadIdx.x == 0) {
        float s = 0.f;
#pragma unroll
        for (int w = 0; w < 8; w++) s += wsum[w];
        atomicAdd(&g_loss[q], s);
    }
}

// ---------------------------------------------------------------------------
// final: quantized_out = x - residual_final; write losses
// ---------------------------------------------------------------------------
__global__ void final_kernel(const float4* __restrict__ x,
                             float* __restrict__ out, int write_extra) {
    const int n4 = M_ * D_ / 4;
    float4* o4 = (float4*)out;
    const float4* r4 = (const float4*)g_residual;
    for (int i = blockIdx.x * blockDim.x + threadIdx.x; i < n4;
         i += gridDim.x * blockDim.x) {
        float4 xv = x[i], rv = r4[i];
        float4 ov;
        ov.x = xv.x - rv.x; ov.y = xv.y - rv.y;
        ov.z = xv.z - rv.z; ov.w = xv.w - rv.w;
        o4[i] = ov;
    }
    if (write_extra && blockIdx.x == 0 && threadIdx.x < Q_)
        out[OUT_LOSS_OFF + threadIdx.x] =
            g_loss[threadIdx.x] * (1.0f / ((float)M_ * (float)D_));
}

// ---------------------------------------------------------------------------
extern "C" void kernel_launch(void* const* d_in, const int* in_sizes, int n_in,
                              void* d_out, int out_size) {
    const float* x   = (const float*)d_in[0];
    const float* cbs = (const float*)d_in[1];
    float* out = (float*)d_out;

    const int full = (int)(OUT_LOSS_OFF + Q_);
    const int write_extra = (out_size >= full) ? 1 : 0;
    float* idx_out = write_extra ? out + OUT_IDX_OFF : nullptr;

    static int attr_done = 0;
    if (!attr_done) {
        cudaFuncSetAttribute(screen_kernel,
                             cudaFuncAttributeMaxDynamicSharedMemorySize,
                             SMEM_BYTES);
        attr_done = 1;
    }

    init_kernel<<<M_ / 8, 256>>>(x);
    prep_kernel<<<(Q_ * C_ * 32) / 256, 256>>>(cbs);
    for (int q = 0; q < Q_; q++) {
        screen_kernel<<<dim3(64, 8), 256, SMEM_BYTES>>>(q);
        rerank_kernel<<<M_ / 8, 256>>>(cbs, idx_out, q, q == Q_ - 1);
    }
    final_kernel<<<512, 256>>>((const float4*)x, out, write_extra);
}

// round 16
// speedup vs baseline: 1.7574x; 1.7574x over previous
#include <cuda_runtime.h>
#include <cuda_fp16.h>
#include <cstdint>

// ---------------------------------------------------------------------------
// Problem constants
// ---------------------------------------------------------------------------
#define B_   8
#define N_   1024
#define D_   512
#define C_   1024
#define Q_   8
#define M_   (B_ * N_)      // 8192 rows
#define D4_  (D_ / 4)

// Output layout (all float32): [quantized_out M*D][indices M*Q][losses Q]
#define OUT_IDX_OFF  ((size_t)M_ * D_)
#define OUT_LOSS_OFF ((size_t)M_ * D_ + (size_t)M_ * Q_)

// rescue margin: screen fp16-dot error (~0.16) + fp16 storage error (~0.13)
#define DELTA 0.75f

// ---------------------------------------------------------------------------
// Scratch (__device__ globals — allocation-free)
// ---------------------------------------------------------------------------
__device__ float g_residual[M_ * D_];
__device__ __half gA0[M_ * D_];            // fp16(residual)
__device__ __half gB0[Q_ * C_ * D_];       // fp16(codebooks)
__device__ float g_e2[Q_ * C_];
__device__ float g_loss[Q_];
__device__ __half g_dots[M_ * C_];         // fp16(-2*dot) matrix (16.7 MB)

// ---------------------------------------------------------------------------
// Arch-neutral PTX helpers (sm_80-level: cp.async / ldmatrix / mma.sync)
// ---------------------------------------------------------------------------
__device__ __forceinline__ uint32_t smem_to_u32(const void* p) {
    uint32_t a;
    asm("{ .reg .u64 t; cvta.to.shared.u64 t, %1; cvt.u32.u64 %0, t; }"
        : "=r"(a) : "l"(p));
    return a;
}
__device__ __forceinline__ void cp16(uint32_t dst, const void* src) {
    asm volatile("cp.async.cg.shared.global [%0], [%1], 16;"
                 :: "r"(dst), "l"(src));
}
#define CP_COMMIT() asm volatile("cp.async.commit_group;" ::: "memory")
#define CP_WAIT(n)  asm volatile("cp.async.wait_group %0;" :: "n"(n) : "memory")

__device__ __forceinline__ void ldm_x4(uint32_t* r, uint32_t addr) {
    asm volatile("ldmatrix.sync.aligned.m8n8.x4.shared.b16 {%0,%1,%2,%3}, [%4];"
                 : "=r"(r[0]), "=r"(r[1]), "=r"(r[2]), "=r"(r[3]) : "r"(addr));
}
__device__ __forceinline__ void mma16816(float* d, const uint32_t* a,
                                         uint32_t b0, uint32_t b1) {
    asm volatile(
        "mma.sync.aligned.m16n8k16.row.col.f32.f16.f16.f32 "
        "{%0,%1,%2,%3}, {%4,%5,%6,%7}, {%8,%9}, {%0,%1,%2,%3};"
        : "+f"(d[0]), "+f"(d[1]), "+f"(d[2]), "+f"(d[3])
        : "r"(a[0]), "r"(a[1]), "r"(a[2]), "r"(a[3]), "r"(b0), "r"(b1));
}

// monotone float -> uint transform (order-preserving, for packed min)
__device__ __forceinline__ uint32_t ford(float f) {
    uint32_t u = __float_as_uint(f);
    return (u & 0x80000000u) ? ~u : (u | 0x80000000u);
}
__device__ __forceinline__ float funord(uint32_t u) {
    return __uint_as_float((u & 0x80000000u) ? (u ^ 0x80000000u) : ~u);
}

// ---------------------------------------------------------------------------
// init: residual = x, fp16 copy, zero loss
// ---------------------------------------------------------------------------
__global__ void init_kernel(const float* __restrict__ x) {
    const int tid = blockIdx.x * blockDim.x + threadIdx.x;
    const int stride = gridDim.x * blockDim.x;
    for (int i = tid; i < M_ * D_; i += stride) {
        float v = x[i];
        g_residual[i] = v;
        gA0[i] = __float2half_rn(v);
    }
    if (tid < Q_) g_loss[tid] = 0.f;
}

// ---------------------------------------------------------------------------
// prep: e2 + fp16 copy for all 8 codebooks (one warp per row)
// ---------------------------------------------------------------------------
__global__ void prep_kernel(const float* __restrict__ cbs) {
    const int w = (blockIdx.x * blockDim.x + threadIdx.x) >> 5;
    const int lane = threadIdx.x & 31;
    if (w >= Q_ * C_) return;
    const float* row = cbs + (size_t)w * D_;
    __half* b0 = gB0 + (size_t)w * D_;
    float s = 0.f;
#pragma unroll
    for (int i = lane; i < D_; i += 32) {
        float v = row[i];
        s = fmaf(v, v, s);
        b0[i] = __float2half_rn(v);
    }
#pragma unroll
    for (int o = 16; o > 0; o >>= 1) s += __shfl_xor_sync(0xffffffffu, s, o);
    if (lane == 0) g_e2[w] = s;
}

// ---------------------------------------------------------------------------
// Screen GEMM: single fp16 product, fp32 accumulate. CTA 128x128, K=512,
// 8 warps @ 64x32, 4-stage cp.async pipeline, k-chunk 32.
// mtile_off selects the M-half this stream owns (grid.x = 32 per half).
// Epilogue writes fp16(-2*dot) to g_dots.
// ---------------------------------------------------------------------------
#define KCH    32
#define NCH    16              // 512 / 32
#define ROWB   80u             // 32 fp16 (64B) + 16B pad
#define TILEB  10240u          // 128 * 80
#define STAGEB 20480u          // A + B tiles
#define SMEM_BYTES 81920u

__global__ void __launch_bounds__(256, 2) screen_kernel(int q, int mtile_off) {
    extern __shared__ __align__(128) char smem[];
    const uint32_t sm = smem_to_u32(smem);

    const int t = threadIdx.x;
    const int lane = t & 31, wid = t >> 5;
    const int warp_m = (wid >> 2) * 64;     // 0 or 64
    const int warp_n = (wid & 3) * 32;      // 0..96
    const int bm0 = (blockIdx.x + mtile_off) * 128;
    const int c0  = blockIdx.y * 128;

    const __half* Bq0 = gB0 + (size_t)q * C_ * D_;

    // loader mapping: row = t>>1 (128 rows), granule g = t&1 (32B half-row)
    const int lrow = t >> 1;
    const int lg   = t & 1;
    const __half* pa = gA0 + (size_t)(bm0 + lrow) * D_ + lg * 16;
    const __half* pb = Bq0 + (size_t)(c0 + lrow) * D_ + lg * 16;
    const uint32_t sdst = sm + lrow * ROWB + lg * 32;

    uint32_t a_off[4];
#pragma unroll
    for (int ma = 0; ma < 4; ma++)
        a_off[ma] = (uint32_t)((warp_m + ma * 16 + (lane & 15)) * ROWB +
                               (lane >> 4) * 16);
    uint32_t b_off[2];
#pragma unroll
    for (int p = 0; p < 2; p++)
        b_off[p] = (uint32_t)((warp_n + p * 16 + ((lane >> 4) << 3) + (lane & 7)) * ROWB +
                              ((lane >> 3) & 1) * 16);

    float acc[4][4][4];
#pragma unroll
    for (int i = 0; i < 4; i++)
#pragma unroll
        for (int j = 0; j < 4; j++)
#pragma unroll
            for (int e = 0; e < 4; e++) acc[i][j][e] = 0.f;

    auto issue_loads = [&](int kk) {
        const uint32_t buf = (uint32_t)(kk & 3) * STAGEB + sdst;
        const int col = kk * KCH;
        cp16(buf,              pa + col);
        cp16(buf + 16,         pa + col + 8);
        cp16(buf + TILEB,      pb + col);
        cp16(buf + TILEB + 16, pb + col + 8);
        CP_COMMIT();
    };

    issue_loads(0); issue_loads(1); issue_loads(2);

    for (int cc = 0; cc < NCH; cc++) {
        if (cc < NCH - 2)       CP_WAIT(2);
        else if (cc == NCH - 2) CP_WAIT(1);
        else                    CP_WAIT(0);
        __syncthreads();

        const uint32_t buf = sm + (uint32_t)(cc & 3) * STAGEB;
#pragma unroll
        for (int k = 0; k < 2; k++) {           // two k=16 steps (bytes +0/+32)
            uint32_t a[4][4], bb[2][4];
#pragma unroll
            for (int ma = 0; ma < 4; ma++)
                ldm_x4(a[ma], buf + a_off[ma] + k * 32);
#pragma unroll
            for (int p = 0; p < 2; p++)
                ldm_x4(bb[p], buf + TILEB + b_off[p] + k * 32);
#pragma unroll
            for (int ma = 0; ma < 4; ma++)
#pragma unroll
                for (int nb = 0; nb < 4; nb++) {
                    const uint32_t* bp = bb[nb >> 1];
                    mma16816(acc[ma][nb], a[ma], bp[(nb & 1) * 2], bp[(nb & 1) * 2 + 1]);
                }
        }
        if (cc + 3 < NCH) issue_loads(cc + 3);
        __syncthreads();
    }

    // epilogue: write fp16(-2*dot) pairs (half2 stores)
    const int g = lane >> 2, tg = lane & 3;
#pragma unroll
    for (int ma = 0; ma < 4; ma++) {
#pragma unroll
        for (int half = 0; half < 2; half++) {
            const int row = bm0 + warp_m + ma * 16 + half * 8 + g;
            __half* krow = g_dots + (size_t)row * C_ + c0 + warp_n;
#pragma unroll
            for (int nb = 0; nb < 4; nb++) {
                __half2 hv = __floats2half2_rn(
                    -2.f * acc[ma][nb][half * 2 + 0],
                    -2.f * acc[ma][nb][half * 2 + 1]);
                *(__half2*)(krow + nb * 8 + tg * 2) = hv;
            }
        }
    }
}

// ---------------------------------------------------------------------------
// rerank + update: one warp per row. Scan approx keys (e2 + fp16 dots),
// exact fp32 re-rank of candidates within DELTA of the row min, then
// residual update / loss / fp16 re-copy / index write.
// row_off selects the M-half this stream owns (grid.x = 512 per half).
// ---------------------------------------------------------------------------
__global__ void __launch_bounds__(256) rerank_kernel(
    const float* __restrict__ cbs, float* __restrict__ idx_out, int q, int last,
    int row_off) {
    const int lane = threadIdx.x & 31, wid = threadIdx.x >> 5;
    const int row = row_off + blockIdx.x * 8 + wid;
    const float* cb = cbs + (size_t)q * C_ * D_;
    __shared__ float wsum[8];
    __shared__ float e2s[C_];

    // cooperative e2 load (shared by all 8 rows of this block)
    {
        const float* e2q = g_e2 + q * C_;
#pragma unroll
        for (int i = 0; i < C_ / 256; i++)
            e2s[threadIdx.x + 256 * i] = e2q[threadIdx.x + 256 * i];
    }
    __syncthreads();

    // residual row, lane-strided
    float res[16];
#pragma unroll
    for (int k = 0; k < 16; k++)
        res[k] = g_residual[(size_t)row * D_ + lane + 32 * k];

    // load this lane's 32 approx keys: e2 + fp16(-2*dot)
    const __half* drow = g_dots + (size_t)row * C_;
    float keys[32];
#pragma unroll
    for (int kp = 0; kp < 32; kp++)
        keys[kp] = e2s[kp * 32 + lane] + __half2float(drow[kp * 32 + lane]);

    // packed min over the row (tie -> smallest index)
    unsigned long long pk = ~0ull;
#pragma unroll
    for (int kp = 0; kp < 32; kp++) {
        unsigned long long p =
            ((unsigned long long)ford(keys[kp]) << 32) | (unsigned)(kp * 32 + lane);
        if (p < pk) pk = p;
    }
#pragma unroll
    for (int o = 16; o > 0; o >>= 1) {
        unsigned long long other = __shfl_xor_sync(0xffffffffu, pk, o);
        if (other < pk) pk = other;
    }
    const float thresh = funord((uint32_t)(pk >> 32)) + DELTA;

    // exact re-rank of margin candidates
    unsigned long long bestx = ~0ull;
#pragma unroll
    for (int kp = 0; kp < 32; kp++) {
        unsigned mask = __ballot_sync(0xffffffffu, keys[kp] <= thresh);
        while (mask) {
            const int b = __ffs(mask) - 1;
            mask &= mask - 1;
            const int cand = kp * 32 + b;
            const float* cr = cb + (size_t)cand * D_;
            float dot = 0.f;
#pragma unroll
            for (int k = 0; k < 16; k++)
                dot = fmaf(res[k], cr[lane + 32 * k], dot);
#pragma unroll
            for (int o = 16; o > 0; o >>= 1)
                dot += __shfl_xor_sync(0xffffffffu, dot, o);
            const float ek = e2s[cand] - 2.f * dot;
            unsigned long long p =
                ((unsigned long long)ford(ek) << 32) | (unsigned)cand;
            if (p < bestx) bestx = p;
        }
    }
    const int bidx = (int)(bestx & 0xFFFFFFFFull);
    if (lane == 0 && idx_out)
        idx_out[(size_t)row * Q_ + q] = (float)bidx;

    // update residual, loss, fp16 copy
    const float* cw = cb + (size_t)bidx * D_;
    float sq = 0.f;
#pragma unroll
    for (int k = 0; k < 16; k++) {
        const int j = lane + 32 * k;
        float rn = res[k] - cw[j];
        g_residual[(size_t)row * D_ + j] = rn;
        sq = fmaf(rn, rn, sq);
        if (!last) gA0[(size_t)row * D_ + j] = __float2half_rn(rn);
    }
#pragma unroll
    for (int o = 16; o > 0; o >>= 1) sq += __shfl_xor_sync(0xffffffffu, sq, o);
    if (lane == 0) wsum[wid] = sq;
    __syncthreads();
    if (threadIdx.x == 0) {
        float s = 0.f;
#pragma unroll
        for (int w = 0; w < 8; w++) s += wsum[w];
        atomicAdd(&g_loss[q], s);
    }
}

// ---------------------------------------------------------------------------
// final: quantized_out = x - residual_final; write losses
// ---------------------------------------------------------------------------
__global__ void final_kernel(const float4* __restrict__ x,
                             float* __restrict__ out, int write_extra) {
    const int n4 = M_ * D_ / 4;
    float4* o4 = (float4*)out;
    const float4* r4 = (const float4*)g_residual;
    for (int i = blockIdx.x * blockDim.x + threadIdx.x; i < n4;
         i += gridDim.x * blockDim.x) {
        float4 xv = x[i], rv = r4[i];
        float4 ov;
        ov.x = xv.x - rv.x; ov.y = xv.y - rv.y;
        ov.z = xv.z - rv.z; ov.w = xv.w - rv.w;
        o4[i] = ov;
    }
    if (write_extra && blockIdx.x == 0 && threadIdx.x < Q_)
        out[OUT_LOSS_OFF + threadIdx.x] =
            g_loss[threadIdx.x] * (1.0f / ((float)M_ * (float)D_));
}

// ---------------------------------------------------------------------------
// launch: two independent half-M chains on two streams (capture-safe fork).
// Stream 0 (legacy): m-tiles [0,32). Stream s1: m-tiles [32,64).
// ---------------------------------------------------------------------------
extern "C" void kernel_launch(void* const* d_in, const int* in_sizes, int n_in,
                              void* d_out, int out_size) {
    const float* x   = (const float*)d_in[0];
    const float* cbs = (const float*)d_in[1];
    float* out = (float*)d_out;

    const int full = (int)(OUT_LOSS_OFF + Q_);
    const int write_extra = (out_size >= full) ? 1 : 0;
    float* idx_out = write_extra ? out + OUT_IDX_OFF : nullptr;

    static cudaStream_t s1;
    static cudaEvent_t evFork, evJoin;
    static int init_done = 0;
    if (!init_done) {
        cudaFuncSetAttribute(screen_kernel,
                             cudaFuncAttributeMaxDynamicSharedMemorySize,
                             SMEM_BYTES);
        cudaStreamCreateWithFlags(&s1, cudaStreamNonBlocking);
        cudaEventCreateWithFlags(&evFork, cudaEventDisableTiming);
        cudaEventCreateWithFlags(&evJoin, cudaEventDisableTiming);
        init_done = 1;
    }

    init_kernel<<<1024, 256>>>(x);
    prep_kernel<<<(Q_ * C_ * 32) / 256, 256>>>(cbs);

    // fork: s1 depends on init+prep
    cudaEventRecord(evFork, 0);
    cudaStreamWaitEvent(s1, evFork, 0);

    for (int q = 0; q < Q_; q++) {
        screen_kernel<<<dim3(32, 8), 256, SMEM_BYTES>>>(q, 0);
        rerank_kernel<<<512, 256>>>(cbs, idx_out, q, q == Q_ - 1, 0);
    }
    for (int q = 0; q < Q_; q++) {
        screen_kernel<<<dim3(32, 8), 256, SMEM_BYTES, s1>>>(q, 32);
        rerank_kernel<<<512, 256, 0, s1>>>(cbs, idx_out, q, q == Q_ - 1, 4096);
    }

    // join: final depends on both chains
    cudaEventRecord(evJoin, s1);
    cudaStreamWaitEvent(0, evJoin, 0);
    final_kernel<<<512, 256>>>((const float4*)x, out, write_extra);
}

// round 17
// speedup vs baseline: 1.9535x; 1.1116x over previous
#include <cuda_runtime.h>
#include <cuda_fp16.h>
#include <cstdint>

// ---------------------------------------------------------------------------
// Problem constants
// ---------------------------------------------------------------------------
#define B_   8
#define N_   1024
#define D_   512
#define C_   1024
#define Q_   8
#define M_   (B_ * N_)      // 8192 rows
#define D4_  (D_ / 4)

// Output layout (all float32): [quantized_out M*D][indices M*Q][losses Q]
#define OUT_IDX_OFF  ((size_t)M_ * D_)
#define OUT_LOSS_OFF ((size_t)M_ * D_ + (size_t)M_ * Q_)

// rescue margin: screen fp16-dot error (~0.16) + fp16 storage error (~0.13)
#define DELTA 0.75f

#define NSTREAM 4
#define MT_PER  16             // m-tiles per chain (64 / 4)
#define ROWS_PER (MT_PER * 128)

// ---------------------------------------------------------------------------
// Scratch (__device__ globals — allocation-free)
// ---------------------------------------------------------------------------
__device__ float g_residual[M_ * D_];
__device__ __half gA0[M_ * D_];            // fp16(residual)
__device__ __half gB0[Q_ * C_ * D_];       // fp16(codebooks)
__device__ float g_e2[Q_ * C_];
__device__ float g_loss[Q_];
__device__ __half g_dots[M_ * C_];         // fp16(-2*dot) matrix (16.7 MB)

// ---------------------------------------------------------------------------
// Arch-neutral PTX helpers (sm_80-level: cp.async / ldmatrix / mma.sync)
// ---------------------------------------------------------------------------
__device__ __forceinline__ uint32_t smem_to_u32(const void* p) {
    uint32_t a;
    asm("{ .reg .u64 t; cvta.to.shared.u64 t, %1; cvt.u32.u64 %0, t; }"
        : "=r"(a) : "l"(p));
    return a;
}
__device__ __forceinline__ void cp16(uint32_t dst, const void* src) {
    asm volatile("cp.async.cg.shared.global [%0], [%1], 16;"
                 :: "r"(dst), "l"(src));
}
#define CP_COMMIT() asm volatile("cp.async.commit_group;" ::: "memory")
#define CP_WAIT(n)  asm volatile("cp.async.wait_group %0;" :: "n"(n) : "memory")

__device__ __forceinline__ void ldm_x4(uint32_t* r, uint32_t addr) {
    asm volatile("ldmatrix.sync.aligned.m8n8.x4.shared.b16 {%0,%1,%2,%3}, [%4];"
                 : "=r"(r[0]), "=r"(r[1]), "=r"(r[2]), "=r"(r[3]) : "r"(addr));
}
__device__ __forceinline__ void mma16816(float* d, const uint32_t* a,
                                         uint32_t b0, uint32_t b1) {
    asm volatile(
        "mma.sync.aligned.m16n8k16.row.col.f32.f16.f16.f32 "
        "{%0,%1,%2,%3}, {%4,%5,%6,%7}, {%8,%9}, {%0,%1,%2,%3};"
        : "+f"(d[0]), "+f"(d[1]), "+f"(d[2]), "+f"(d[3])
        : "r"(a[0]), "r"(a[1]), "r"(a[2]), "r"(a[3]), "r"(b0), "r"(b1));
}

// monotone float -> uint transform (order-preserving, for exact-rerank min)
__device__ __forceinline__ uint32_t ford(float f) {
    uint32_t u = __float_as_uint(f);
    return (u & 0x80000000u) ? ~u : (u | 0x80000000u);
}

// ---------------------------------------------------------------------------
// init: residual = x, fp16 copy, zero loss
// ---------------------------------------------------------------------------
__global__ void init_kernel(const float* __restrict__ x) {
    const int tid = blockIdx.x * blockDim.x + threadIdx.x;
    const int stride = gridDim.x * blockDim.x;
    for (int i = tid; i < M_ * D_; i += stride) {
        float v = x[i];
        g_residual[i] = v;
        gA0[i] = __float2half_rn(v);
    }
    if (tid < Q_) g_loss[tid] = 0.f;
}

// ---------------------------------------------------------------------------
// prep: e2 + fp16 copy for all 8 codebooks (one warp per row)
// ---------------------------------------------------------------------------
__global__ void prep_kernel(const float* __restrict__ cbs) {
    const int w = (blockIdx.x * blockDim.x + threadIdx.x) >> 5;
    const int lane = threadIdx.x & 31;
    if (w >= Q_ * C_) return;
    const float* row = cbs + (size_t)w * D_;
    __half* b0 = gB0 + (size_t)w * D_;
    float s = 0.f;
#pragma unroll
    for (int i = lane; i < D_; i += 32) {
        float v = row[i];
        s = fmaf(v, v, s);
        b0[i] = __float2half_rn(v);
    }
#pragma unroll
    for (int o = 16; o > 0; o >>= 1) s += __shfl_xor_sync(0xffffffffu, s, o);
    if (lane == 0) g_e2[w] = s;
}

// ---------------------------------------------------------------------------
// Screen GEMM: single fp16 product, fp32 accumulate. CTA 128x128, K=512,
// 8 warps @ 64x32, 4-stage cp.async pipeline, k-chunk 32.
// mtile_off selects the M-quarter this stream owns (grid.x = 16 per quarter).
// Epilogue writes fp16(-2*dot) to g_dots.
// ---------------------------------------------------------------------------
#define KCH    32
#define NCH    16              // 512 / 32
#define ROWB   80u             // 32 fp16 (64B) + 16B pad
#define TILEB  10240u          // 128 * 80
#define STAGEB 20480u          // A + B tiles
#define SMEM_BYTES 81920u

__global__ void __launch_bounds__(256, 2) screen_kernel(int q, int mtile_off) {
    extern __shared__ __align__(128) char smem[];
    const uint32_t sm = smem_to_u32(smem);

    const int t = threadIdx.x;
    const int lane = t & 31, wid = t >> 5;
    const int warp_m = (wid >> 2) * 64;     // 0 or 64
    const int warp_n = (wid & 3) * 32;      // 0..96
    const int bm0 = (blockIdx.x + mtile_off) * 128;
    const int c0  = blockIdx.y * 128;

    const __half* Bq0 = gB0 + (size_t)q * C_ * D_;

    // loader mapping: row = t>>1 (128 rows), granule g = t&1 (32B half-row)
    const int lrow = t >> 1;
    const int lg   = t & 1;
    const __half* pa = gA0 + (size_t)(bm0 + lrow) * D_ + lg * 16;
    const __half* pb = Bq0 + (size_t)(c0 + lrow) * D_ + lg * 16;
    const uint32_t sdst = sm + lrow * ROWB + lg * 32;

    uint32_t a_off[4];
#pragma unroll
    for (int ma = 0; ma < 4; ma++)
        a_off[ma] = (uint32_t)((warp_m + ma * 16 + (lane & 15)) * ROWB +
                               (lane >> 4) * 16);
    uint32_t b_off[2];
#pragma unroll
    for (int p = 0; p < 2; p++)
        b_off[p] = (uint32_t)((warp_n + p * 16 + ((lane >> 4) << 3) + (lane & 7)) * ROWB +
                              ((lane >> 3) & 1) * 16);

    float acc[4][4][4];
#pragma unroll
    for (int i = 0; i < 4; i++)
#pragma unroll
        for (int j = 0; j < 4; j++)
#pragma unroll
            for (int e = 0; e < 4; e++) acc[i][j][e] = 0.f;

    auto issue_loads = [&](int kk) {
        const uint32_t buf = (uint32_t)(kk & 3) * STAGEB + sdst;
        const int col = kk * KCH;
        cp16(buf,              pa + col);
        cp16(buf + 16,         pa + col + 8);
        cp16(buf + TILEB,      pb + col);
        cp16(buf + TILEB + 16, pb + col + 8);
        CP_COMMIT();
    };

    issue_loads(0); issue_loads(1); issue_loads(2);

    for (int cc = 0; cc < NCH; cc++) {
        if (cc < NCH - 2)       CP_WAIT(2);
        else if (cc == NCH - 2) CP_WAIT(1);
        else                    CP_WAIT(0);
        __syncthreads();

        const uint32_t buf = sm + (uint32_t)(cc & 3) * STAGEB;
#pragma unroll
        for (int k = 0; k < 2; k++) {           // two k=16 steps (bytes +0/+32)
            uint32_t a[4][4], bb[2][4];
#pragma unroll
            for (int ma = 0; ma < 4; ma++)
                ldm_x4(a[ma], buf + a_off[ma] + k * 32);
#pragma unroll
            for (int p = 0; p < 2; p++)
                ldm_x4(bb[p], buf + TILEB + b_off[p] + k * 32);
#pragma unroll
            for (int ma = 0; ma < 4; ma++)
#pragma unroll
                for (int nb = 0; nb < 4; nb++) {
                    const uint32_t* bp = bb[nb >> 1];
                    mma16816(acc[ma][nb], a[ma], bp[(nb & 1) * 2], bp[(nb & 1) * 2 + 1]);
                }
        }
        if (cc + 3 < NCH) issue_loads(cc + 3);
        __syncthreads();
    }

    // epilogue: write fp16(-2*dot) pairs (half2 stores)
    const int g = lane >> 2, tg = lane & 3;
#pragma unroll
    for (int ma = 0; ma < 4; ma++) {
#pragma unroll
        for (int half = 0; half < 2; half++) {
            const int row = bm0 + warp_m + ma * 16 + half * 8 + g;
            __half* krow = g_dots + (size_t)row * C_ + c0 + warp_n;
#pragma unroll
            for (int nb = 0; nb < 4; nb++) {
                __half2 hv = __floats2half2_rn(
                    -2.f * acc[ma][nb][half * 2 + 0],
                    -2.f * acc[ma][nb][half * 2 + 1]);
                *(__half2*)(krow + nb * 8 + tg * 2) = hv;
            }
        }
    }
}

// ---------------------------------------------------------------------------
// rerank + update: one warp per row. fminf scan for the row-min threshold,
// exact fp32 re-rank (float4 loads, packed-u64 index tie-break) of all
// candidates within DELTA, then residual update / loss / fp16 re-copy.
// row_off selects the M-quarter this stream owns.
// ---------------------------------------------------------------------------
__global__ void __launch_bounds__(256) rerank_kernel(
    const float* __restrict__ cbs, float* __restrict__ idx_out, int q, int last,
    int row_off) {
    const int lane = threadIdx.x & 31, wid = threadIdx.x >> 5;
    const int row = row_off + blockIdx.x * 8 + wid;
    const float* cb = cbs + (size_t)q * C_ * D_;
    __shared__ float wsum[8];
    __shared__ float e2s[C_];

    // cooperative e2 load (shared by all 8 rows of this block)
    {
        const float* e2q = g_e2 + q * C_;
#pragma unroll
        for (int i = 0; i < C_ / 256; i++)
            e2s[threadIdx.x + 256 * i] = e2q[threadIdx.x + 256 * i];
    }
    __syncthreads();

    // residual row (float4, lane-strided)
    const float4* rres = (const float4*)(g_residual + (size_t)row * D_);
    float4 res4[4];
#pragma unroll
    for (int k = 0; k < 4; k++) res4[k] = rres[lane + 32 * k];

    // approx keys: e2 + fp16(-2*dot); min value only
    const __half* drow = g_dots + (size_t)row * C_;
    float keys[32];
    float mn = 3.4e38f;
#pragma unroll
    for (int kp = 0; kp < 32; kp++) {
        keys[kp] = e2s[kp * 32 + lane] + __half2float(drow[kp * 32 + lane]);
        mn = fminf(mn, keys[kp]);
    }
#pragma unroll
    for (int o = 16; o > 0; o >>= 1)
        mn = fminf(mn, __shfl_xor_sync(0xffffffffu, mn, o));
    const float thresh = mn + DELTA;

    // exact fp32 re-rank of margin candidates (first-min via index tie-break)
    unsigned long long bestx = ~0ull;
#pragma unroll
    for (int kp = 0; kp < 32; kp++) {
        unsigned mask = __ballot_sync(0xffffffffu, keys[kp] <= thresh);
        while (mask) {
            const int b = __ffs(mask) - 1;
            mask &= mask - 1;
            const int cand = kp * 32 + b;
            const float4* cr4 = (const float4*)(cb + (size_t)cand * D_);
            float dot = 0.f;
#pragma unroll
            for (int k = 0; k < 4; k++) {
                const float4 c4 = cr4[lane + 32 * k];
                dot = fmaf(res4[k].x, c4.x, dot); dot = fmaf(res4[k].y, c4.y, dot);
                dot = fmaf(res4[k].z, c4.z, dot); dot = fmaf(res4[k].w, c4.w, dot);
            }
#pragma unroll
            for (int o = 16; o > 0; o >>= 1)
                dot += __shfl_xor_sync(0xffffffffu, dot, o);
            const float ek = e2s[cand] - 2.f * dot;
            unsigned long long p =
                ((unsigned long long)ford(ek) << 32) | (unsigned)cand;
            if (p < bestx) bestx = p;
        }
    }
    const int bidx = (int)(bestx & 0xFFFFFFFFull);
    if (lane == 0 && idx_out)
        idx_out[(size_t)row * Q_ + q] = (float)bidx;

    // update residual, loss, fp16 copy
    const float4* cw4 = (const float4*)(cb + (size_t)bidx * D_);
    float4* wres = (float4*)(g_residual + (size_t)row * D_);
    float sq = 0.f;
#pragma unroll
    for (int k = 0; k < 4; k++) {
        const int j = lane + 32 * k;
        const float4 c4 = cw4[j];
        float4 rn;
        rn.x = res4[k].x - c4.x; rn.y = res4[k].y - c4.y;
        rn.z = res4[k].z - c4.z; rn.w = res4[k].w - c4.w;
        wres[j] = rn;
        sq = fmaf(rn.x, rn.x, sq); sq = fmaf(rn.y, rn.y, sq);
        sq = fmaf(rn.z, rn.z, sq); sq = fmaf(rn.w, rn.w, sq);
        if (!last) {
            __half2 h2a = __floats2half2_rn(rn.x, rn.y);
            __half2 h2b = __floats2half2_rn(rn.z, rn.w);
            *(uint2*)&gA0[(size_t)row * D_ + (size_t)j * 4] =
                make_uint2(*(uint32_t*)&h2a, *(uint32_t*)&h2b);
        }
    }
#pragma unroll
    for (int o = 16; o > 0; o >>= 1) sq += __shfl_xor_sync(0xffffffffu, sq, o);
    if (lane == 0) wsum[wid] = sq;
    __syncthreads();
    if (threadIdx.x == 0) {
        float s = 0.f;
#pragma unroll
        for (int w = 0; w < 8; w++) s += wsum[w];
        atomicAdd(&g_loss[q], s);
    }
}

// ---------------------------------------------------------------------------
// final: quantized_out = x - residual_final; write losses
// ---------------------------------------------------------------------------
__global__ void final_kernel(const float4* __restrict__ x,
                             float* __restrict__ out, int write_extra) {
    const int n4 = M_ * D_ / 4;
    float4* o4 = (float4*)out;
    const float4* r4 = (const float4*)g_residual;
    for (int i = blockIdx.x * blockDim.x + threadIdx.x; i < n4;
         i += gridDim.x * blockDim.x) {
        float4 xv = x[i], rv = r4[i];
        float4 ov;
        ov.x = xv.x - rv.x; ov.y = xv.y - rv.y;
        ov.z = xv.z - rv.z; ov.w = xv.w - rv.w;
        o4[i] = ov;
    }
    if (write_extra && blockIdx.x == 0 && threadIdx.x < Q_)
        out[OUT_LOSS_OFF + threadIdx.x] =
            g_loss[threadIdx.x] * (1.0f / ((float)M_ * (float)D_));
}

// ---------------------------------------------------------------------------
// launch: four independent quarter-M chains on four streams
// (capture-safe event fork/join). Chain i owns m-tiles [i*16, (i+1)*16).
// ---------------------------------------------------------------------------
extern "C" void kernel_launch(void* const* d_in, const int* in_sizes, int n_in,
                              void* d_out, int out_size) {
    const float* x   = (const float*)d_in[0];
    const float* cbs = (const float*)d_in[1];
    float* out = (float*)d_out;

    const int full = (int)(OUT_LOSS_OFF + Q_);
    const int write_extra = (out_size >= full) ? 1 : 0;
    float* idx_out = write_extra ? out + OUT_IDX_OFF : nullptr;

    static cudaStream_t st[NSTREAM - 1];
    static cudaEvent_t evFork;
    static cudaEvent_t evJoin[NSTREAM - 1];
    static int init_done = 0;
    if (!init_done) {
        cudaFuncSetAttribute(screen_kernel,
                             cudaFuncAttributeMaxDynamicSharedMemorySize,
                             SMEM_BYTES);
        for (int i = 0; i < NSTREAM - 1; i++) {
            cudaStreamCreateWithFlags(&st[i], cudaStreamNonBlocking);
            cudaEventCreateWithFlags(&evJoin[i], cudaEventDisableTiming);
        }
        cudaEventCreateWithFlags(&evFork, cudaEventDisableTiming);
        init_done = 1;
    }

    init_kernel<<<1024, 256>>>(x);
    prep_kernel<<<(Q_ * C_ * 32) / 256, 256>>>(cbs);

    // fork: side streams depend on init+prep
    cudaEventRecord(evFork, 0);
    for (int i = 0; i < NSTREAM - 1; i++)
        cudaStreamWaitEvent(st[i], evFork, 0);

    // chain 0 on the legacy stream
    for (int q = 0; q < Q_; q++) {
        screen_kernel<<<dim3(MT_PER, 8), 256, SMEM_BYTES>>>(q, 0);
        rerank_kernel<<<ROWS_PER / 8, 256>>>(cbs, idx_out, q, q == Q_ - 1, 0);
    }
    // chains 1..3 on side streams
    for (int i = 0; i < NSTREAM - 1; i++) {
        const int mt0 = (i + 1) * MT_PER;
        const int r0  = (i + 1) * ROWS_PER;
        for (int q = 0; q < Q_; q++) {
            screen_kernel<<<dim3(MT_PER, 8), 256, SMEM_BYTES, st[i]>>>(q, mt0);
            rerank_kernel<<<ROWS_PER / 8, 256, 0, st[i]>>>(cbs, idx_out, q,
                                                           q == Q_ - 1, r0);
        }
        cudaEventRecord(evJoin[i], st[i]);
    }

    // join: final depends on all chains
    for (int i = 0; i < NSTREAM - 1; i++)
        cudaStreamWaitEvent(0, evJoin[i], 0);
    final_kernel<<<512, 256>>>((const float4*)x, out, write_extra);
}